// round 2
// baseline (speedup 1.0000x reference)
#include <cuda_runtime.h>

// ---------------------------------------------------------------------------
// YOLO loss, S=14 grid, N=4096 images. Memory-bound reduction:
//   read ~177 MB, emit 5 floats.
// has_object_map arrives as int32 (0/1) — confirmed by rel_err forensics R1.
// ---------------------------------------------------------------------------

__device__ float g_acc[4];  // [0]=reg_raw  [1]=contain  [2]=noobj_raw  [3]=cls

__global__ void yolo_zero_acc() {
    if (threadIdx.x < 4) g_acc[threadIdx.x] = 0.0f;
}

__global__ __launch_bounds__(256) void yolo_main(
    const float* __restrict__ pred,   // (NC, 30)
    const float* __restrict__ tbox,   // (NC, 4)
    const float* __restrict__ tcls,   // (NC, 20)
    const int*   __restrict__ objmap, // (NC,)  int32 0/1
    int ncell)
{
    int cell = blockIdx.x * 256 + threadIdx.x;

    float reg = 0.0f, contain = 0.0f, noobj = 0.0f, cls = 0.0f;

    if (cell < ncell) {
        // ---- loads (pred row is 120 B => 8 B aligned => float2) ----
        const float2* p2 = reinterpret_cast<const float2*>(pred + (size_t)cell * 30);
        float p[30];
        #pragma unroll
        for (int i = 0; i < 15; i++) {
            float2 v = __ldg(p2 + i);
            p[2*i]   = v.x;
            p[2*i+1] = v.y;
        }
        float4 tb = __ldg(reinterpret_cast<const float4*>(tbox + (size_t)cell * 4));
        float tc[20];
        const float4* tc4 = reinterpret_cast<const float4*>(tcls + (size_t)cell * 20);
        #pragma unroll
        for (int i = 0; i < 5; i++) {
            float4 v = __ldg(tc4 + i);
            tc[4*i]   = v.x;
            tc[4*i+1] = v.y;
            tc[4*i+2] = v.z;
            tc[4*i+3] = v.w;
        }
        float obj = (objmap[cell] != 0) ? 1.0f : 0.0f;

        // ---- class loss ----
        float csum = 0.0f;
        #pragma unroll
        for (int j = 0; j < 20; j++) {
            float d = p[10 + j] - tc[j];
            csum += d * d;
        }
        cls = obj * csum;

        // ---- no-object confidence loss (raw; *0.5 in finalize) ----
        noobj = (1.0f - obj) * (p[4] * p[4] + p[9] * p[9]);

        // ---- IoU selection ----
        const float invS = 1.0f / 14.0f;
        float tx1 = tb.x * invS - 0.5f * tb.z;
        float ty1 = tb.y * invS - 0.5f * tb.w;
        float tx2 = tb.x * invS + 0.5f * tb.z;
        float ty2 = tb.y * invS + 0.5f * tb.w;
        float ta  = (tx2 - tx1) * (ty2 - ty1);

        float iou[2];
        #pragma unroll
        for (int b = 0; b < 2; b++) {
            float bx = p[5*b + 0], by = p[5*b + 1];
            float bw = p[5*b + 2], bh = p[5*b + 3];
            float x1 = bx * invS - 0.5f * bw;
            float y1 = by * invS - 0.5f * bh;
            float x2 = bx * invS + 0.5f * bw;
            float y2 = by * invS + 0.5f * bh;
            float lx = fmaxf(x1, tx1), ly = fmaxf(y1, ty1);
            float rx = fminf(x2, tx2), ry = fminf(y2, ty2);
            float w  = fmaxf(rx - lx, 0.0f);
            float h  = fmaxf(ry - ly, 0.0f);
            float inter = w * h;
            float a1 = (x2 - x1) * (y2 - y1);
            iou[b] = inter / (a1 + ta - inter);
        }

        bool  take1    = iou[0] > iou[1];
        float best_iou = take1 ? iou[0] : iou[1];
        int   off      = take1 ? 0 : 5;
        float bx = p[off + 0], by = p[off + 1];
        float bw = p[off + 2], bh = p[off + 3];
        float bc = p[off + 4];

        float dx = bx - tb.x;
        float dy = by - tb.y;
        float sw = sqrtf(bw) - sqrtf(tb.z);
        float sh = sqrtf(bh) - sqrtf(tb.w);
        reg = obj * (dx * dx + dy * dy + sw * sw + sh * sh);  // raw; *5 in finalize

        float dc = bc - best_iou;
        contain = obj * dc * dc;
    }

    // ---- warp reduction ----
    #pragma unroll
    for (int o = 16; o > 0; o >>= 1) {
        reg     += __shfl_down_sync(0xffffffffu, reg,     o);
        contain += __shfl_down_sync(0xffffffffu, contain, o);
        noobj   += __shfl_down_sync(0xffffffffu, noobj,   o);
        cls     += __shfl_down_sync(0xffffffffu, cls,     o);
    }

    __shared__ float sm[8][4];
    int w = threadIdx.x >> 5;
    int l = threadIdx.x & 31;
    if (l == 0) {
        sm[w][0] = reg;
        sm[w][1] = contain;
        sm[w][2] = noobj;
        sm[w][3] = cls;
    }
    __syncthreads();

    if (threadIdx.x < 4) {
        float s = 0.0f;
        #pragma unroll
        for (int i = 0; i < 8; i++) s += sm[i][threadIdx.x];
        atomicAdd(&g_acc[threadIdx.x], s);
    }
}

__global__ void yolo_finalize(float* __restrict__ out) {
    const float L_COORD = 5.0f;
    const float L_NOOBJ = 0.5f;
    float reg     = L_COORD * g_acc[0];
    float contain = g_acc[1];
    float noobj   = L_NOOBJ * g_acc[2];
    float cls     = g_acc[3];
    float total   = reg + contain + noobj + cls;
    float invN    = 1.0f / 4096.0f;
    out[0] = total   * invN;
    out[1] = reg     * invN;
    out[2] = contain * invN;
    out[3] = noobj   * invN;
    out[4] = cls     * invN;
}

extern "C" void kernel_launch(void* const* d_in, const int* in_sizes, int n_in,
                              void* d_out, int out_size) {
    const float* pred = (const float*)d_in[0];
    const float* tbox = (const float*)d_in[1];
    const float* tcls = (const float*)d_in[2];
    const int*   obj  = (const int*)d_in[3];
    int ncell = in_sizes[3];  // N * S * S = 802816

    yolo_zero_acc<<<1, 32>>>();
    yolo_main<<<(ncell + 255) / 256, 256>>>(pred, tbox, tcls, obj, ncell);
    yolo_finalize<<<1, 1>>>((float*)d_out);
}

// round 4
// speedup vs baseline: 1.4132x; 1.4132x over previous
#include <cuda_runtime.h>

// ---------------------------------------------------------------------------
// YOLO loss, S=14, N=4096. DRAM-bound reduction: read ~177 MB -> 5 floats.
// R3: smem-staged pred (coalesced float4), linearized coalesced cls pass,
// single kernel with last-block finalize. L1 wavefronts/warp ~55 (ideal).
// ---------------------------------------------------------------------------

__device__ float    g_acc[4];   // zero-initialized; reset by last block each call
__device__ unsigned g_done;     // zero-initialized; reset by last block each call

#define TPB 256
#define PRED_F  (TPB * 30)      // floats of pred per block  (7680 = 30 KB)
#define PRED_V4 (PRED_F / 4)    // 1920 float4
#define TCLS_V4 (TPB * 20 / 4)  // 1280 float4

__global__ __launch_bounds__(TPB) void yolo_fused(
    const float* __restrict__ pred,   // (NC, 30)
    const float* __restrict__ tbox,   // (NC, 4)
    const float* __restrict__ tcls,   // (NC, 20)
    const int*   __restrict__ objmap, // (NC,)  int32 0/1
    float*       __restrict__ out,
    int ncell)
{
    __shared__ float s_pred[PRED_F];   // 30720 B
    __shared__ float s_obj[TPB];       //  1024 B

    const int tid  = threadIdx.x;
    const int cell0 = blockIdx.x * TPB;
    const int cell  = cell0 + tid;

    // ---- stage pred chunk: fully coalesced float4 loads ----
    {
        const float4* gp = reinterpret_cast<const float4*>(pred + (size_t)cell0 * 30);
        float4*       sp = reinterpret_cast<float4*>(s_pred);
        #pragma unroll
        for (int k = 0; k < 8; k++) {
            int idx = tid + k * TPB;
            if (idx < PRED_V4) sp[idx] = __ldg(gp + idx);
        }
        s_obj[tid] = (cell < ncell && objmap[cell] != 0) ? 1.0f : 0.0f;
    }
    __syncthreads();

    float reg = 0.0f, contain = 0.0f, noobj = 0.0f, cls = 0.0f;

    // ---- per-cell box terms (pred from smem, conflict-free LDS.64) ----
    if (cell < ncell) {
        float p[10];
        const float2* sp2 = reinterpret_cast<const float2*>(s_pred + tid * 30);
        #pragma unroll
        for (int i = 0; i < 5; i++) {
            float2 v = sp2[i];
            p[2*i]   = v.x;
            p[2*i+1] = v.y;
        }
        float conf1 = p[4];
        float conf2 = p[9];
        float obj   = s_obj[tid];

        float4 tb = __ldg(reinterpret_cast<const float4*>(tbox + (size_t)cell * 4));

        noobj = (1.0f - obj) * (conf1 * conf1 + conf2 * conf2);

        const float invS = 1.0f / 14.0f;
        float tx1 = tb.x * invS - 0.5f * tb.z;
        float ty1 = tb.y * invS - 0.5f * tb.w;
        float tx2 = tb.x * invS + 0.5f * tb.z;
        float ty2 = tb.y * invS + 0.5f * tb.w;
        float ta  = (tx2 - tx1) * (ty2 - ty1);

        float iou[2];
        #pragma unroll
        for (int b = 0; b < 2; b++) {
            float bx = p[5*b + 0], by = p[5*b + 1];
            float bw = p[5*b + 2], bh = p[5*b + 3];
            float x1 = bx * invS - 0.5f * bw;
            float y1 = by * invS - 0.5f * bh;
            float x2 = bx * invS + 0.5f * bw;
            float y2 = by * invS + 0.5f * bh;
            float lx = fmaxf(x1, tx1), ly = fmaxf(y1, ty1);
            float rx = fminf(x2, tx2), ry = fminf(y2, ty2);
            float w  = fmaxf(rx - lx, 0.0f);
            float h  = fmaxf(ry - ly, 0.0f);
            float inter = w * h;
            float a1 = (x2 - x1) * (y2 - y1);
            iou[b] = inter / (a1 + ta - inter);
        }

        bool  take1    = iou[0] > iou[1];
        float best_iou = take1 ? iou[0] : iou[1];
        int   off      = take1 ? 0 : 5;

        float dx = p[off + 0] - tb.x;
        float dy = p[off + 1] - tb.y;
        float sw = sqrtf(p[off + 2]) - sqrtf(tb.z);
        float sh = sqrtf(p[off + 3]) - sqrtf(tb.w);
        reg = obj * (dx * dx + dy * dy + sw * sw + sh * sh);  // *5 in finalize

        float dc = p[off + 4] - best_iou;
        contain = obj * dc * dc;
    }

    // ---- cls term: linearized, coalesced float4 tcls loads ----
    {
        const float4* gt = reinterpret_cast<const float4*>(tcls + (size_t)cell0 * 20);
        #pragma unroll
        for (int k = 0; k < 5; k++) {
            int idx4 = tid + k * TPB;           // 0..1279 within block
            int c    = idx4 / 5;                 // local cell
            int j    = (idx4 % 5) * 4;           // class offset 0,4,8,12,16
            float4 t = __ldg(gt + idx4);
            const float2* pp = reinterpret_cast<const float2*>(s_pred + c * 30 + 10 + j);
            float2 a = pp[0], b = pp[1];
            float d0 = a.x - t.x;
            float d1 = a.y - t.y;
            float d2 = b.x - t.z;
            float d3 = b.y - t.w;
            cls += s_obj[c] * (d0*d0 + d1*d1 + d2*d2 + d3*d3);
        }
    }

    // ---- warp + block reduction ----
    #pragma unroll
    for (int o = 16; o > 0; o >>= 1) {
        reg     += __shfl_down_sync(0xffffffffu, reg,     o);
        contain += __shfl_down_sync(0xffffffffu, contain, o);
        noobj   += __shfl_down_sync(0xffffffffu, noobj,   o);
        cls     += __shfl_down_sync(0xffffffffu, cls,     o);
    }

    __shared__ float sm[8][4];
    int w = tid >> 5, l = tid & 31;
    if (l == 0) { sm[w][0] = reg; sm[w][1] = contain; sm[w][2] = noobj; sm[w][3] = cls; }
    __syncthreads();

    if (tid < 4) {
        float s = 0.0f;
        #pragma unroll
        for (int i = 0; i < 8; i++) s += sm[i][tid];
        atomicAdd(&g_acc[tid], s);
    }
    __syncthreads();

    // ---- last block finalizes and resets state for next graph replay ----
    __shared__ bool is_last;
    if (tid == 0) {
        __threadfence();
        unsigned t = atomicAdd(&g_done, 1u);
        is_last = (t == gridDim.x - 1);
    }
    __syncthreads();

    if (is_last && tid == 0) {
        const float L_COORD = 5.0f;
        const float L_NOOBJ = 0.5f;
        float regf     = L_COORD * g_acc[0];
        float containf = g_acc[1];
        float noobjf   = L_NOOBJ * g_acc[2];
        float clsf     = g_acc[3];
        float total    = regf + containf + noobjf + clsf;
        const float invN = 1.0f / 4096.0f;
        out[0] = total    * invN;
        out[1] = regf     * invN;
        out[2] = containf * invN;
        out[3] = noobjf   * invN;
        out[4] = clsf     * invN;
        // reset for the next invocation / graph replay
        g_acc[0] = 0.0f; g_acc[1] = 0.0f; g_acc[2] = 0.0f; g_acc[3] = 0.0f;
        g_done = 0u;
    }
}

extern "C" void kernel_launch(void* const* d_in, const int* in_sizes, int n_in,
                              void* d_out, int out_size) {
    const float* pred = (const float*)d_in[0];
    const float* tbox = (const float*)d_in[1];
    const float* tcls = (const float*)d_in[2];
    const int*   obj  = (const int*)d_in[3];
    int ncell = in_sizes[3];  // N*S*S = 802816 = 3136 * 256

    int nblocks = (ncell + TPB - 1) / TPB;
    yolo_fused<<<nblocks, TPB>>>(pred, tbox, tcls, obj, (float*)d_out, ncell);
}

// round 5
// speedup vs baseline: 1.4798x; 1.0471x over previous
#include <cuda_runtime.h>

// ---------------------------------------------------------------------------
// YOLO loss, S=14, N=4096. DRAM-bound reduction: read ~177 MB -> 5 floats.
// R3: smem-staged pred (coalesced float4), linearized coalesced cls pass,
// single kernel with last-block finalize. L1 wavefronts/warp ~55 (ideal).
// ---------------------------------------------------------------------------

__device__ float    g_acc[4];   // zero-initialized; reset by last block each call
__device__ unsigned g_done;     // zero-initialized; reset by last block each call

#define TPB 256
#define PRED_F  (TPB * 30)      // floats of pred per block  (7680 = 30 KB)
#define PRED_V4 (PRED_F / 4)    // 1920 float4
#define TCLS_V4 (TPB * 20 / 4)  // 1280 float4

__global__ __launch_bounds__(TPB) void yolo_fused(
    const float* __restrict__ pred,   // (NC, 30)
    const float* __restrict__ tbox,   // (NC, 4)
    const float* __restrict__ tcls,   // (NC, 20)
    const int*   __restrict__ objmap, // (NC,)  int32 0/1
    float*       __restrict__ out,
    int ncell)
{
    __shared__ float s_pred[PRED_F];   // 30720 B
    __shared__ float s_obj[TPB];       //  1024 B

    const int tid  = threadIdx.x;
    const int cell0 = blockIdx.x * TPB;
    const int cell  = cell0 + tid;

    // ---- stage pred chunk: fully coalesced float4 loads ----
    {
        const float4* gp = reinterpret_cast<const float4*>(pred + (size_t)cell0 * 30);
        float4*       sp = reinterpret_cast<float4*>(s_pred);
        #pragma unroll
        for (int k = 0; k < 8; k++) {
            int idx = tid + k * TPB;
            if (idx < PRED_V4) sp[idx] = __ldg(gp + idx);
        }
        s_obj[tid] = (cell < ncell && objmap[cell] != 0) ? 1.0f : 0.0f;
    }
    __syncthreads();

    float reg = 0.0f, contain = 0.0f, noobj = 0.0f, cls = 0.0f;

    // ---- per-cell box terms (pred from smem, conflict-free LDS.64) ----
    if (cell < ncell) {
        float p[10];
        const float2* sp2 = reinterpret_cast<const float2*>(s_pred + tid * 30);
        #pragma unroll
        for (int i = 0; i < 5; i++) {
            float2 v = sp2[i];
            p[2*i]   = v.x;
            p[2*i+1] = v.y;
        }
        float conf1 = p[4];
        float conf2 = p[9];
        float obj   = s_obj[tid];

        float4 tb = __ldg(reinterpret_cast<const float4*>(tbox + (size_t)cell * 4));

        noobj = (1.0f - obj) * (conf1 * conf1 + conf2 * conf2);

        const float invS = 1.0f / 14.0f;
        float tx1 = tb.x * invS - 0.5f * tb.z;
        float ty1 = tb.y * invS - 0.5f * tb.w;
        float tx2 = tb.x * invS + 0.5f * tb.z;
        float ty2 = tb.y * invS + 0.5f * tb.w;
        float ta  = (tx2 - tx1) * (ty2 - ty1);

        float iou[2];
        #pragma unroll
        for (int b = 0; b < 2; b++) {
            float bx = p[5*b + 0], by = p[5*b + 1];
            float bw = p[5*b + 2], bh = p[5*b + 3];
            float x1 = bx * invS - 0.5f * bw;
            float y1 = by * invS - 0.5f * bh;
            float x2 = bx * invS + 0.5f * bw;
            float y2 = by * invS + 0.5f * bh;
            float lx = fmaxf(x1, tx1), ly = fmaxf(y1, ty1);
            float rx = fminf(x2, tx2), ry = fminf(y2, ty2);
            float w  = fmaxf(rx - lx, 0.0f);
            float h  = fmaxf(ry - ly, 0.0f);
            float inter = w * h;
            float a1 = (x2 - x1) * (y2 - y1);
            iou[b] = inter / (a1 + ta - inter);
        }

        bool  take1    = iou[0] > iou[1];
        float best_iou = take1 ? iou[0] : iou[1];
        int   off      = take1 ? 0 : 5;

        float dx = p[off + 0] - tb.x;
        float dy = p[off + 1] - tb.y;
        float sw = sqrtf(p[off + 2]) - sqrtf(tb.z);
        float sh = sqrtf(p[off + 3]) - sqrtf(tb.w);
        reg = obj * (dx * dx + dy * dy + sw * sw + sh * sh);  // *5 in finalize

        float dc = p[off + 4] - best_iou;
        contain = obj * dc * dc;
    }

    // ---- cls term: linearized, coalesced float4 tcls loads ----
    {
        const float4* gt = reinterpret_cast<const float4*>(tcls + (size_t)cell0 * 20);
        #pragma unroll
        for (int k = 0; k < 5; k++) {
            int idx4 = tid + k * TPB;           // 0..1279 within block
            int c    = idx4 / 5;                 // local cell
            int j    = (idx4 % 5) * 4;           // class offset 0,4,8,12,16
            float4 t = __ldg(gt + idx4);
            const float2* pp = reinterpret_cast<const float2*>(s_pred + c * 30 + 10 + j);
            float2 a = pp[0], b = pp[1];
            float d0 = a.x - t.x;
            float d1 = a.y - t.y;
            float d2 = b.x - t.z;
            float d3 = b.y - t.w;
            cls += s_obj[c] * (d0*d0 + d1*d1 + d2*d2 + d3*d3);
        }
    }

    // ---- warp + block reduction ----
    #pragma unroll
    for (int o = 16; o > 0; o >>= 1) {
        reg     += __shfl_down_sync(0xffffffffu, reg,     o);
        contain += __shfl_down_sync(0xffffffffu, contain, o);
        noobj   += __shfl_down_sync(0xffffffffu, noobj,   o);
        cls     += __shfl_down_sync(0xffffffffu, cls,     o);
    }

    __shared__ float sm[8][4];
    int w = tid >> 5, l = tid & 31;
    if (l == 0) { sm[w][0] = reg; sm[w][1] = contain; sm[w][2] = noobj; sm[w][3] = cls; }
    __syncthreads();

    if (tid < 4) {
        float s = 0.0f;
        #pragma unroll
        for (int i = 0; i < 8; i++) s += sm[i][tid];
        atomicAdd(&g_acc[tid], s);
    }
    __syncthreads();

    // ---- last block finalizes and resets state for next graph replay ----
    __shared__ bool is_last;
    if (tid == 0) {
        __threadfence();
        unsigned t = atomicAdd(&g_done, 1u);
        is_last = (t == gridDim.x - 1);
    }
    __syncthreads();

    if (is_last && tid == 0) {
        const float L_COORD = 5.0f;
        const float L_NOOBJ = 0.5f;
        float regf     = L_COORD * g_acc[0];
        float containf = g_acc[1];
        float noobjf   = L_NOOBJ * g_acc[2];
        float clsf     = g_acc[3];
        float total    = regf + containf + noobjf + clsf;
        const float invN = 1.0f / 4096.0f;
        out[0] = total    * invN;
        out[1] = regf     * invN;
        out[2] = containf * invN;
        out[3] = noobjf   * invN;
        out[4] = clsf     * invN;
        // reset for the next invocation / graph replay
        g_acc[0] = 0.0f; g_acc[1] = 0.0f; g_acc[2] = 0.0f; g_acc[3] = 0.0f;
        g_done = 0u;
    }
}

extern "C" void kernel_launch(void* const* d_in, const int* in_sizes, int n_in,
                              void* d_out, int out_size) {
    const float* pred = (const float*)d_in[0];
    const float* tbox = (const float*)d_in[1];
    const float* tcls = (const float*)d_in[2];
    const int*   obj  = (const int*)d_in[3];
    int ncell = in_sizes[3];  // N*S*S = 802816 = 3136 * 256

    int nblocks = (ncell + TPB - 1) / TPB;
    yolo_fused<<<nblocks, TPB>>>(pred, tbox, tcls, obj, (float*)d_out, ncell);
}

// round 6
// speedup vs baseline: 1.4812x; 1.0010x over previous
#include <cuda_runtime.h>

// ---------------------------------------------------------------------------
// YOLO loss, S=14, N=4096. DRAM-bound reduction: read ~177 MB -> 5 floats.
// R3: smem-staged pred (coalesced float4), linearized coalesced cls pass,
// single kernel with last-block finalize. L1 wavefronts/warp ~55 (ideal).
// ---------------------------------------------------------------------------

__device__ float    g_acc[4];   // zero-initialized; reset by last block each call
__device__ unsigned g_done;     // zero-initialized; reset by last block each call

#define TPB 256
#define PRED_F  (TPB * 30)      // floats of pred per block  (7680 = 30 KB)
#define PRED_V4 (PRED_F / 4)    // 1920 float4
#define TCLS_V4 (TPB * 20 / 4)  // 1280 float4

__global__ __launch_bounds__(TPB) void yolo_fused(
    const float* __restrict__ pred,   // (NC, 30)
    const float* __restrict__ tbox,   // (NC, 4)
    const float* __restrict__ tcls,   // (NC, 20)
    const int*   __restrict__ objmap, // (NC,)  int32 0/1
    float*       __restrict__ out,
    int ncell)
{
    __shared__ float s_pred[PRED_F];   // 30720 B
    __shared__ float s_obj[TPB];       //  1024 B

    const int tid  = threadIdx.x;
    const int cell0 = blockIdx.x * TPB;
    const int cell  = cell0 + tid;

    // ---- stage pred chunk: fully coalesced float4 loads ----
    {
        const float4* gp = reinterpret_cast<const float4*>(pred + (size_t)cell0 * 30);
        float4*       sp = reinterpret_cast<float4*>(s_pred);
        #pragma unroll
        for (int k = 0; k < 8; k++) {
            int idx = tid + k * TPB;
            if (idx < PRED_V4) sp[idx] = __ldg(gp + idx);
        }
        s_obj[tid] = (cell < ncell && objmap[cell] != 0) ? 1.0f : 0.0f;
    }
    __syncthreads();

    float reg = 0.0f, contain = 0.0f, noobj = 0.0f, cls = 0.0f;

    // ---- per-cell box terms (pred from smem, conflict-free LDS.64) ----
    if (cell < ncell) {
        float p[10];
        const float2* sp2 = reinterpret_cast<const float2*>(s_pred + tid * 30);
        #pragma unroll
        for (int i = 0; i < 5; i++) {
            float2 v = sp2[i];
            p[2*i]   = v.x;
            p[2*i+1] = v.y;
        }
        float conf1 = p[4];
        float conf2 = p[9];
        float obj   = s_obj[tid];

        float4 tb = __ldg(reinterpret_cast<const float4*>(tbox + (size_t)cell * 4));

        noobj = (1.0f - obj) * (conf1 * conf1 + conf2 * conf2);

        const float invS = 1.0f / 14.0f;
        float tx1 = tb.x * invS - 0.5f * tb.z;
        float ty1 = tb.y * invS - 0.5f * tb.w;
        float tx2 = tb.x * invS + 0.5f * tb.z;
        float ty2 = tb.y * invS + 0.5f * tb.w;
        float ta  = (tx2 - tx1) * (ty2 - ty1);

        float iou[2];
        #pragma unroll
        for (int b = 0; b < 2; b++) {
            float bx = p[5*b + 0], by = p[5*b + 1];
            float bw = p[5*b + 2], bh = p[5*b + 3];
            float x1 = bx * invS - 0.5f * bw;
            float y1 = by * invS - 0.5f * bh;
            float x2 = bx * invS + 0.5f * bw;
            float y2 = by * invS + 0.5f * bh;
            float lx = fmaxf(x1, tx1), ly = fmaxf(y1, ty1);
            float rx = fminf(x2, tx2), ry = fminf(y2, ty2);
            float w  = fmaxf(rx - lx, 0.0f);
            float h  = fmaxf(ry - ly, 0.0f);
            float inter = w * h;
            float a1 = (x2 - x1) * (y2 - y1);
            iou[b] = inter / (a1 + ta - inter);
        }

        bool  take1    = iou[0] > iou[1];
        float best_iou = take1 ? iou[0] : iou[1];
        int   off      = take1 ? 0 : 5;

        float dx = p[off + 0] - tb.x;
        float dy = p[off + 1] - tb.y;
        float sw = sqrtf(p[off + 2]) - sqrtf(tb.z);
        float sh = sqrtf(p[off + 3]) - sqrtf(tb.w);
        reg = obj * (dx * dx + dy * dy + sw * sw + sh * sh);  // *5 in finalize

        float dc = p[off + 4] - best_iou;
        contain = obj * dc * dc;
    }

    // ---- cls term: linearized, coalesced float4 tcls loads ----
    {
        const float4* gt = reinterpret_cast<const float4*>(tcls + (size_t)cell0 * 20);
        #pragma unroll
        for (int k = 0; k < 5; k++) {
            int idx4 = tid + k * TPB;           // 0..1279 within block
            int c    = idx4 / 5;                 // local cell
            int j    = (idx4 % 5) * 4;           // class offset 0,4,8,12,16
            float4 t = __ldg(gt + idx4);
            const float2* pp = reinterpret_cast<const float2*>(s_pred + c * 30 + 10 + j);
            float2 a = pp[0], b = pp[1];
            float d0 = a.x - t.x;
            float d1 = a.y - t.y;
            float d2 = b.x - t.z;
            float d3 = b.y - t.w;
            cls += s_obj[c] * (d0*d0 + d1*d1 + d2*d2 + d3*d3);
        }
    }

    // ---- warp + block reduction ----
    #pragma unroll
    for (int o = 16; o > 0; o >>= 1) {
        reg     += __shfl_down_sync(0xffffffffu, reg,     o);
        contain += __shfl_down_sync(0xffffffffu, contain, o);
        noobj   += __shfl_down_sync(0xffffffffu, noobj,   o);
        cls     += __shfl_down_sync(0xffffffffu, cls,     o);
    }

    __shared__ float sm[8][4];
    int w = tid >> 5, l = tid & 31;
    if (l == 0) { sm[w][0] = reg; sm[w][1] = contain; sm[w][2] = noobj; sm[w][3] = cls; }
    __syncthreads();

    if (tid < 4) {
        float s = 0.0f;
        #pragma unroll
        for (int i = 0; i < 8; i++) s += sm[i][tid];
        atomicAdd(&g_acc[tid], s);
    }
    __syncthreads();

    // ---- last block finalizes and resets state for next graph replay ----
    __shared__ bool is_last;
    if (tid == 0) {
        __threadfence();
        unsigned t = atomicAdd(&g_done, 1u);
        is_last = (t == gridDim.x - 1);
    }
    __syncthreads();

    if (is_last && tid == 0) {
        const float L_COORD = 5.0f;
        const float L_NOOBJ = 0.5f;
        float regf     = L_COORD * g_acc[0];
        float containf = g_acc[1];
        float noobjf   = L_NOOBJ * g_acc[2];
        float clsf     = g_acc[3];
        float total    = regf + containf + noobjf + clsf;
        const float invN = 1.0f / 4096.0f;
        out[0] = total    * invN;
        out[1] = regf     * invN;
        out[2] = containf * invN;
        out[3] = noobjf   * invN;
        out[4] = clsf     * invN;
        // reset for the next invocation / graph replay
        g_acc[0] = 0.0f; g_acc[1] = 0.0f; g_acc[2] = 0.0f; g_acc[3] = 0.0f;
        g_done = 0u;
    }
}

extern "C" void kernel_launch(void* const* d_in, const int* in_sizes, int n_in,
                              void* d_out, int out_size) {
    const float* pred = (const float*)d_in[0];
    const float* tbox = (const float*)d_in[1];
    const float* tcls = (const float*)d_in[2];
    const int*   obj  = (const int*)d_in[3];
    int ncell = in_sizes[3];  // N*S*S = 802816 = 3136 * 256

    int nblocks = (ncell + TPB - 1) / TPB;
    yolo_fused<<<nblocks, TPB>>>(pred, tbox, tcls, obj, (float*)d_out, ncell);
}